// round 5
// baseline (speedup 1.0000x reference)
#include <cuda_runtime.h>

// out = clip(x + laplace * mask, 0, 1), elementwise, 38,535,168 fp32.
// HBM-roofline streaming kernel: 3 reads + 1 write, 616.6 MB irreducible.
// R4: unguarded bulk kernel (exact divisibility handled host-side), VPT=4
// with 12 front-batched streaming LDGs per thread for long HBM read bursts.

#define VPT 4       // float4s per thread
#define THREADS 256

// Bulk kernel: assumes every thread has VPT full float4s (no bounds checks).
__global__ void rrn_clip_bulk(const float4* __restrict__ x,
                              const float4* __restrict__ lap,
                              const float4* __restrict__ mask,
                              float4* __restrict__ out) {
    int base = (blockIdx.x * THREADS) * VPT + threadIdx.x;

    float4 xv[VPT], lv[VPT], mv[VPT];
    #pragma unroll
    for (int j = 0; j < VPT; j++) {
        int i = base + j * THREADS;
        xv[j] = __ldcs(x + i);
        lv[j] = __ldcs(lap + i);
        mv[j] = __ldcs(mask + i);
    }
    #pragma unroll
    for (int j = 0; j < VPT; j++) {
        int i = base + j * THREADS;
        float4 r;
        r.x = __saturatef(fmaf(lv[j].x, mv[j].x, xv[j].x));
        r.y = __saturatef(fmaf(lv[j].y, mv[j].y, xv[j].y));
        r.z = __saturatef(fmaf(lv[j].z, mv[j].z, xv[j].z));
        r.w = __saturatef(fmaf(lv[j].w, mv[j].w, xv[j].w));
        __stcs(out + i, r);
    }
}

// Generic scalar remainder (covers non-divisible n; not launched for this shape).
__global__ void rrn_clip_rem(const float* __restrict__ x,
                             const float* __restrict__ lap,
                             const float* __restrict__ mask,
                             float* __restrict__ out,
                             int start, int n) {
    int i = start + blockIdx.x * blockDim.x + threadIdx.x;
    if (i >= n) return;
    out[i] = __saturatef(fmaf(__ldcs(lap + i), __ldcs(mask + i), __ldcs(x + i)));
}

extern "C" void kernel_launch(void* const* d_in, const int* in_sizes, int n_in,
                              void* d_out, int out_size) {
    // metadata order: x, eps (dead scalar), laplace_noise, mask
    const float* x    = (const float*)d_in[0];
    const float* lap  = (const float*)d_in[2];
    const float* mask = (const float*)d_in[3];
    float* out        = (float*)d_out;

    int n = in_sizes[0];
    const int elems_per_block = THREADS * VPT * 4;   // 4096 floats per block
    int full_blocks = n / elems_per_block;

    if (full_blocks > 0) {
        rrn_clip_bulk<<<full_blocks, THREADS>>>(
            (const float4*)x, (const float4*)lap, (const float4*)mask,
            (float4*)out);
    }
    int done = full_blocks * elems_per_block;
    int rem = n - done;
    if (rem > 0) {
        int blocks = (rem + THREADS - 1) / THREADS;
        rrn_clip_rem<<<blocks, THREADS>>>(x, lap, mask, out, done, n);
    }
}

// round 7
// speedup vs baseline: 1.0033x; 1.0033x over previous
#include <cuda_runtime.h>

// out = clip(x + laplace * mask, 0, 1), elementwise, 38,535,168 fp32.
// HBM-roofline streaming kernel: 3 reads + 1 write, 616.6 MB irreducible.
// R6 = R5 resubmit (infra failure last round): VPT=2 (measured optimum of
// {1,2,4}) with UNGUARDED bulk kernel — exact divisibility enforced
// host-side, predication chain deleted.

#define VPT 2       // float4s per thread (sweep: 1->84.3us, 2->83.0us, 4->83.7us)
#define THREADS 256

// Bulk kernel: every thread owns VPT full float4s, no bounds checks.
__global__ void rrn_clip_bulk(const float4* __restrict__ x,
                              const float4* __restrict__ lap,
                              const float4* __restrict__ mask,
                              float4* __restrict__ out) {
    int base = (blockIdx.x * THREADS) * VPT + threadIdx.x;

    float4 xv[VPT], lv[VPT], mv[VPT];
    #pragma unroll
    for (int j = 0; j < VPT; j++) {
        int i = base + j * THREADS;
        xv[j] = __ldcs(x + i);
        lv[j] = __ldcs(lap + i);
        mv[j] = __ldcs(mask + i);
    }
    #pragma unroll
    for (int j = 0; j < VPT; j++) {
        int i = base + j * THREADS;
        float4 r;
        r.x = __saturatef(fmaf(lv[j].x, mv[j].x, xv[j].x));
        r.y = __saturatef(fmaf(lv[j].y, mv[j].y, xv[j].y));
        r.z = __saturatef(fmaf(lv[j].z, mv[j].z, xv[j].z));
        r.w = __saturatef(fmaf(lv[j].w, mv[j].w, xv[j].w));
        __stcs(out + i, r);
    }
}

// Generic scalar remainder (covers non-divisible n; not launched for this shape).
__global__ void rrn_clip_rem(const float* __restrict__ x,
                             const float* __restrict__ lap,
                             const float* __restrict__ mask,
                             float* __restrict__ out,
                             int start, int n) {
    int i = start + blockIdx.x * blockDim.x + threadIdx.x;
    if (i >= n) return;
    out[i] = __saturatef(fmaf(__ldcs(lap + i), __ldcs(mask + i), __ldcs(x + i)));
}

extern "C" void kernel_launch(void* const* d_in, const int* in_sizes, int n_in,
                              void* d_out, int out_size) {
    // metadata order: x, eps (dead scalar), laplace_noise, mask
    const float* x    = (const float*)d_in[0];
    const float* lap  = (const float*)d_in[2];
    const float* mask = (const float*)d_in[3];
    float* out        = (float*)d_out;

    int n = in_sizes[0];
    const int elems_per_block = THREADS * VPT * 4;   // 2048 floats per block
    int full_blocks = n / elems_per_block;           // 18816 for this shape, rem=0

    if (full_blocks > 0) {
        rrn_clip_bulk<<<full_blocks, THREADS>>>(
            (const float4*)x, (const float4*)lap, (const float4*)mask,
            (float4*)out);
    }
    int done = full_blocks * elems_per_block;
    int rem = n - done;
    if (rem > 0) {
        int blocks = (rem + THREADS - 1) / THREADS;
        rrn_clip_rem<<<blocks, THREADS>>>(x, lap, mask, out, done, n);
    }
}

// round 9
// speedup vs baseline: 1.0080x; 1.0047x over previous
#include <cuda_runtime.h>

// out = clip(x + laplace * mask, 0, 1), elementwise, 38,535,168 fp32.
// HBM-roofline streaming kernel: 3 reads + 1 write, 616.6 MB irreducible.
// R7: 256-bit LDG/STG (sm_100+ LDG.E.256 via ld.global.v8.f32) with
// streaming (.cs) hints. One 32B chunk per thread per operand; unguarded
// bulk path (exact divisibility enforced host-side).

#define THREADS 256

struct f8 { float v[8]; };

__device__ __forceinline__ f8 ldg256_cs(const float* p) {
    f8 r;
    asm volatile(
        "ld.global.cs.v8.f32 {%0,%1,%2,%3,%4,%5,%6,%7}, [%8];"
        : "=f"(r.v[0]), "=f"(r.v[1]), "=f"(r.v[2]), "=f"(r.v[3]),
          "=f"(r.v[4]), "=f"(r.v[5]), "=f"(r.v[6]), "=f"(r.v[7])
        : "l"(p));
    return r;
}

__device__ __forceinline__ void stg256_cs(float* p, const f8& r) {
    asm volatile(
        "st.global.cs.v8.f32 [%0], {%1,%2,%3,%4,%5,%6,%7,%8};"
        :: "l"(p),
           "f"(r.v[0]), "f"(r.v[1]), "f"(r.v[2]), "f"(r.v[3]),
           "f"(r.v[4]), "f"(r.v[5]), "f"(r.v[6]), "f"(r.v[7])
        : "memory");
}

// Bulk kernel: every thread owns one 8-float chunk, no bounds checks.
__global__ void rrn_clip_bulk(const float* __restrict__ x,
                              const float* __restrict__ lap,
                              const float* __restrict__ mask,
                              float* __restrict__ out) {
    long long i = ((long long)blockIdx.x * THREADS + threadIdx.x) * 8;

    f8 xv = ldg256_cs(x + i);
    f8 lv = ldg256_cs(lap + i);
    f8 mv = ldg256_cs(mask + i);

    f8 r;
    #pragma unroll
    for (int j = 0; j < 8; j++)
        r.v[j] = __saturatef(fmaf(lv.v[j], mv.v[j], xv.v[j]));

    stg256_cs(out + i, r);
}

// Generic scalar remainder (covers non-divisible n; not launched for this shape).
__global__ void rrn_clip_rem(const float* __restrict__ x,
                             const float* __restrict__ lap,
                             const float* __restrict__ mask,
                             float* __restrict__ out,
                             int start, int n) {
    int i = start + blockIdx.x * blockDim.x + threadIdx.x;
    if (i >= n) return;
    out[i] = __saturatef(fmaf(__ldcs(lap + i), __ldcs(mask + i), __ldcs(x + i)));
}

extern "C" void kernel_launch(void* const* d_in, const int* in_sizes, int n_in,
                              void* d_out, int out_size) {
    // metadata order: x, eps (dead scalar), laplace_noise, mask
    const float* x    = (const float*)d_in[0];
    const float* lap  = (const float*)d_in[2];
    const float* mask = (const float*)d_in[3];
    float* out        = (float*)d_out;

    int n = in_sizes[0];
    const int elems_per_block = THREADS * 8;         // 2048 floats per block
    int full_blocks = n / elems_per_block;           // 18816 for this shape, rem=0

    if (full_blocks > 0) {
        rrn_clip_bulk<<<full_blocks, THREADS>>>(x, lap, mask, out);
    }
    int done = full_blocks * elems_per_block;
    int rem = n - done;
    if (rem > 0) {
        int blocks = (rem + THREADS - 1) / THREADS;
        rrn_clip_rem<<<blocks, THREADS>>>(x, lap, mask, out, done, n);
    }
}